// round 1
// baseline (speedup 1.0000x reference)
#include <cuda_runtime.h>

#define H 200
#define W 704
#define HW (H*W)            // 140800
#define HP 202
#define WP 712              // left pad 4, right pad 4 (alignment)
#define CS (HP*WP)          // 143824 floats per channel (padded plane)
#define NC 256
#define NBOX 128

// ---------------- persistent device scratch (zero-initialized at load) ----------------
__device__ float g_bufx[(size_t)NC * CS];   // ~147 MB
__device__ float g_bufy[(size_t)NC * CS];   // ~147 MB (halo stays 0 forever)
__device__ float g_obj[NBOX * NC];
__device__ float g_edge[NBOX * 16];         // per box, per edge: ax, ay, vx, vy
__device__ int   g_nact;
__device__ int   g_pix[HW];
__device__ uint4 g_mask[HW];

// ---------------- MLP: obj[n,c] = ((relu(relu(f@W1+b1)@W2+b2)@W3)+b3)*score -----------
__global__ void mlp_kernel(const float* __restrict__ box, const float* __restrict__ score,
                           const float* __restrict__ w1, const float* __restrict__ b1,
                           const float* __restrict__ w2, const float* __restrict__ b2,
                           const float* __restrict__ w3, const float* __restrict__ b3)
{
    __shared__ float f[25];
    __shared__ float h1[256];
    __shared__ float h2[256];
    int n = blockIdx.x, c = threadIdx.x;
    if (c < 25) f[c] = (c < 24) ? box[n * 24 + c] : score[n];
    __syncthreads();
    float a = b1[c];
#pragma unroll
    for (int k = 0; k < 25; ++k) a = fmaf(f[k], w1[k * 256 + c], a);
    h1[c] = fmaxf(a, 0.0f);
    __syncthreads();
    a = b2[c];
    for (int k = 0; k < 256; ++k) a = fmaf(h1[k], w2[k * 256 + c], a);
    h2[c] = fmaxf(a, 0.0f);
    __syncthreads();
    a = b3[c];
    for (int k = 0; k < 256; ++k) a = fmaf(h2[k], w3[k * 256 + c], a);
    g_obj[n * 256 + c] = a * score[n];
}

// ---------------- box corner -> grid-space edge params; reset compaction counter ------
__global__ void edge_kernel(const float* __restrict__ box)
{
    int n = threadIdx.x;
    if (n == 0) g_nact = 0;
    if (n < NBOX) {
        float gx[4], gy[4];
#pragma unroll
        for (int e = 0; e < 4; ++e) {
            gx[e] = __fdiv_rn(__fsub_rn(box[n * 24 + e * 3 + 0], -140.8f), 0.4f);
            gy[e] = __fdiv_rn(__fsub_rn(box[n * 24 + e * 3 + 1], -40.0f), 0.4f);
        }
#pragma unroll
        for (int e = 0; e < 4; ++e) {
            int e1 = (e + 1) & 3;
            g_edge[n * 16 + e * 4 + 0] = gx[e];
            g_edge[n * 16 + e * 4 + 1] = gy[e];
            g_edge[n * 16 + e * 4 + 2] = __fsub_rn(gx[e1], gx[e]);
            g_edge[n * 16 + e * 4 + 3] = __fsub_rn(gy[e1], gy[e]);
        }
    }
}

// ---------------- zero the X buffer (float4 grid-stride) ------------------------------
__global__ void zero_kernel(float4* p, int n4)
{
    int i = blockIdx.x * blockDim.x + threadIdx.x;
    int stride = gridDim.x * blockDim.x;
    for (; i < n4; i += stride) p[i] = make_float4(0.f, 0.f, 0.f, 0.f);
}

// ---------------- per-pixel inside mask + compaction ----------------------------------
__global__ void mask_kernel()
{
    __shared__ float se[NBOX * 16];
    int tid = threadIdx.x;
    for (int i = tid; i < NBOX * 16; i += blockDim.x) se[i] = g_edge[i];
    __syncthreads();

    int p = blockIdx.x * 256 + tid;
    if (p >= HW) return;
    int h = p / W;
    int w = p - h * W;
    float cy = (float)h + 0.5f;
    float cx = (float)w + 0.5f;

    unsigned mw[4];
    int cnt = 0;
#pragma unroll
    for (int wi = 0; wi < 4; ++wi) {
        unsigned m = 0;
        for (int b = 0; b < 32; ++b) {
            int n = wi * 32 + b;
            const float* e = &se[n * 16];
            bool ins = true;
#pragma unroll
            for (int k = 0; k < 4; ++k) {
                float ax = e[k * 4 + 0], ay = e[k * 4 + 1];
                float vx = e[k * 4 + 2], vy = e[k * 4 + 3];
                // mirror reference op order exactly (no FMA contraction)
                float c = __fsub_rn(__fmul_rn(vx, __fsub_rn(cy, ay)),
                                    __fmul_rn(vy, __fsub_rn(cx, ax)));
                ins = ins && (c >= 0.0f);
            }
            if (ins) m |= (1u << b);
        }
        mw[wi] = m;
        cnt += __popc(m);
    }
    if (cnt) {
        int pos = atomicAdd(&g_nact, 1);
        g_pix[pos] = p;
        g_mask[pos] = make_uint4(mw[0], mw[1], mw[2], mw[3]);
    }
}

// ---------------- scatter obj sums / counts into X (active pixels only) ---------------
__global__ void fill_kernel()
{
    int c = threadIdx.x;   // channel
    int nact = g_nact;
    for (int i = blockIdx.x; i < nact; i += gridDim.x) {
        int p = g_pix[i];
        uint4 mm = g_mask[i];
        int cnt = __popc(mm.x) + __popc(mm.y) + __popc(mm.z) + __popc(mm.w);
        float acc = 0.0f;
        unsigned m;
        m = mm.x; while (m) { int b = __ffs(m) - 1; m &= m - 1; acc += g_obj[(b)       * NC + c]; }
        m = mm.y; while (m) { int b = __ffs(m) - 1; m &= m - 1; acc += g_obj[(b + 32)  * NC + c]; }
        m = mm.z; while (m) { int b = __ffs(m) - 1; m &= m - 1; acc += g_obj[(b + 64)  * NC + c]; }
        m = mm.w; while (m) { int b = __ffs(m) - 1; m &= m - 1; acc += g_obj[(b + 96)  * NC + c]; }
        int h = p / W;
        int w = p - h * W;
        g_bufx[(size_t)c * CS + (h + 1) * WP + w + 4] = acc / (float)cnt;
    }
}

// ---------------- fused conv3x3 + BN (+residual) + ReLU -------------------------------
// Block: 256 threads. Tile: 64 co x (8h x 32w). Per thread: 8co x 8px register tile.
__global__ __launch_bounds__(256, 2)
void conv_bn_kernel(const float* __restrict__ in,
                    const float* __restrict__ wgt,
                    const float* __restrict__ bng, const float* __restrict__ bnb,
                    const float* __restrict__ bnm, const float* __restrict__ bnv,
                    const float* resid, float* out,
                    int out_cs, int out_rs, int out_roff, int out_coff, int has_res)
{
    __shared__ float sw[4 * 9 * 64];    // [ci][k][co]
    __shared__ float sx[4 * 10 * 44];   // [ci][row 0..9][col 0..33 (+pad)]

    int tid = threadIdx.x;
    int cg  = tid >> 5;       // warp id -> co subgroup (broadcast weight loads)
    int sub = tid & 31;
    int r   = sub >> 2;       // row 0..7
    int wg  = sub & 3;        // col group (8 px each)

    int co0 = blockIdx.z * 64;
    int h0  = blockIdx.y * 8;
    int w0  = blockIdx.x * 32;

    float acc[8][8];
#pragma unroll
    for (int i = 0; i < 8; ++i)
#pragma unroll
        for (int j = 0; j < 8; ++j) acc[i][j] = 0.0f;

    const float* wbase = wgt + (size_t)co0 * 2304;

    for (int cc = 0; cc < 64; ++cc) {
        int ci0 = cc << 2;
        __syncthreads();
        // stage input patch: 4ci x 10 rows x 34 cols
        for (int idx = tid; idx < 1360; idx += 256) {
            int ci = idx / 340;
            int rr = idx - ci * 340;
            int i  = rr / 34;
            int j  = rr - i * 34;
            sx[(ci * 10 + i) * 44 + j] =
                in[(size_t)(ci0 + ci) * CS + (size_t)(h0 + i) * WP + (w0 + 3) + j];
        }
        // stage weights: 64co x 4ci x 9, coalesced over 36-float runs per co
        for (int idx = tid; idx < 2304; idx += 256) {
            int co = idx / 36;
            int t  = idx - co * 36;
            int ci = t / 9;
            int k  = t - ci * 9;
            sw[(ci * 9 + k) * 64 + co] = wbase[(size_t)co * 2304 + (ci0 + ci) * 9 + k];
        }
        __syncthreads();
#pragma unroll 1
        for (int ci = 0; ci < 4; ++ci) {
#pragma unroll
            for (int kh = 0; kh < 3; ++kh) {
                const float* xr = &sx[(ci * 10 + r + kh) * 44 + (wg << 3)];
                float4 xa = *(const float4*)(xr);
                float4 xb = *(const float4*)(xr + 4);
                float2 xc = *(const float2*)(xr + 8);
                float x[10] = {xa.x, xa.y, xa.z, xa.w, xb.x, xb.y, xb.z, xb.w, xc.x, xc.y};
#pragma unroll
                for (int kw = 0; kw < 3; ++kw) {
                    const float* wr = &sw[(ci * 9 + kh * 3 + kw) * 64 + (cg << 3)];
                    float4 wa = *(const float4*)(wr);
                    float4 wb = *(const float4*)(wr + 4);
                    float wv[8] = {wa.x, wa.y, wa.z, wa.w, wb.x, wb.y, wb.z, wb.w};
#pragma unroll
                    for (int co = 0; co < 8; ++co)
#pragma unroll
                        for (int p = 0; p < 8; ++p)
                            acc[co][p] = fmaf(wv[co], x[p + kw], acc[co][p]);
                }
            }
        }
    }

    // epilogue: BN affine, optional residual, ReLU, float4 stores
    int hq  = h0 + r;
    int wq0 = w0 + (wg << 3);
#pragma unroll
    for (int co = 0; co < 8; ++co) {
        int c = co0 + (cg << 3) + co;
        float sc = bng[c] * rsqrtf(bnv[c] + 1e-5f);
        float sh = bnb[c] - bnm[c] * sc;
        float v[8];
#pragma unroll
        for (int p = 0; p < 8; ++p) v[p] = fmaf(acc[co][p], sc, sh);
        if (has_res) {
            const float* rp = resid + (size_t)c * CS + (size_t)(hq + 1) * WP + wq0 + 4;
            float4 r0 = *(const float4*)rp;
            float4 r1 = *(const float4*)(rp + 4);
            v[0] += r0.x; v[1] += r0.y; v[2] += r0.z; v[3] += r0.w;
            v[4] += r1.x; v[5] += r1.y; v[6] += r1.z; v[7] += r1.w;
        }
#pragma unroll
        for (int p = 0; p < 8; ++p) v[p] = fmaxf(v[p], 0.0f);
        float* op = out + (size_t)c * out_cs + (size_t)(hq + out_roff) * out_rs + wq0 + out_coff;
        *(float4*)(op)     = make_float4(v[0], v[1], v[2], v[3]);
        *(float4*)(op + 4) = make_float4(v[4], v[5], v[6], v[7]);
    }
}

// ---------------- host launcher -------------------------------------------------------
extern "C" void kernel_launch(void* const* d_in, const int* in_sizes, int n_in,
                              void* d_out, int out_size)
{
    const float* box   = (const float*)d_in[0];
    const float* score = (const float*)d_in[1];
    const float* w1 = (const float*)d_in[2];
    const float* b1 = (const float*)d_in[3];
    const float* w2 = (const float*)d_in[4];
    const float* b2 = (const float*)d_in[5];
    const float* w3 = (const float*)d_in[6];
    const float* b3 = (const float*)d_in[7];
    const float* cw = (const float*)d_in[8];
    const float* bg = (const float*)d_in[9];
    const float* bb = (const float*)d_in[10];
    const float* bm = (const float*)d_in[11];
    const float* bv = (const float*)d_in[12];

    float *X = nullptr, *Y = nullptr;
    cudaGetSymbolAddress((void**)&X, g_bufx);
    cudaGetSymbolAddress((void**)&Y, g_bufy);

    mlp_kernel<<<128, 256>>>(box, score, w1, b1, w2, b2, w3, b3);
    edge_kernel<<<1, 128>>>(box);
    zero_kernel<<<4096, 256>>>((float4*)X, (int)((size_t)NC * CS / 4));
    mask_kernel<<<HW / 256, 256>>>();
    fill_kernel<<<1024, 256>>>();

    dim3 cgrid(22, 25, 4);   // 704/32, 200/8, 256/64
    for (int blk = 0; blk < 3; ++blk) {
        const float* wA = cw + (size_t)(blk * 2 + 0) * NC * NC * 9;
        const float* wB = cw + (size_t)(blk * 2 + 1) * NC * NC * 9;
        int oA = (blk * 2 + 0) * NC;
        int oB = (blk * 2 + 1) * NC;
        // y = relu(bn(conv(x)))
        conv_bn_kernel<<<cgrid, 256>>>(X, wA, bg + oA, bb + oA, bm + oA, bv + oA,
                                       nullptr, Y, CS, WP, 1, 4, 0);
        // x = relu(bn(conv(y)) + x)   (last block writes unpadded d_out)
        float* op; int ocs, ors, orf, ocf;
        if (blk < 2) { op = X; ocs = CS; ors = WP; orf = 1; ocf = 4; }
        else         { op = (float*)d_out; ocs = HW; ors = W; orf = 0; ocf = 0; }
        conv_bn_kernel<<<cgrid, 256>>>(Y, wB, bg + oB, bb + oB, bm + oB, bv + oB,
                                       X, op, ocs, ors, orf, ocf, 1);
    }
}

// round 2
// speedup vs baseline: 1.0045x; 1.0045x over previous
#include <cuda_runtime.h>

#define H 200
#define W 704
#define HW (H*W)            // 140800
#define HP 202
#define WP 712              // left pad 4, right pad 4 (alignment)
#define CS (HP*WP)          // 143824 floats per channel (padded plane)
#define NC 256
#define NBOX 128

// ---------------- persistent device scratch (zero-initialized at load) ----------------
__device__ float g_bufx[(size_t)NC * CS];   // ~147 MB
__device__ float g_bufy[(size_t)NC * CS];   // ~147 MB (halo stays 0 forever)
__device__ float g_obj[NBOX * NC];
__device__ float g_edge[NBOX * 16];         // per box, per edge: ax, ay, vx, vy
__device__ int   g_nact;
__device__ int   g_pix[HW];
__device__ uint4 g_mask[HW];

// ---------------- MLP: obj[n,c] = ((relu(relu(f@W1+b1)@W2+b2)@W3)+b3)*score -----------
__global__ void mlp_kernel(const float* __restrict__ box, const float* __restrict__ score,
                           const float* __restrict__ w1, const float* __restrict__ b1,
                           const float* __restrict__ w2, const float* __restrict__ b2,
                           const float* __restrict__ w3, const float* __restrict__ b3)
{
    __shared__ float f[25];
    __shared__ float h1[256];
    __shared__ float h2[256];
    int n = blockIdx.x, c = threadIdx.x;
    if (c < 25) f[c] = (c < 24) ? box[n * 24 + c] : score[n];
    __syncthreads();
    float a = b1[c];
#pragma unroll
    for (int k = 0; k < 25; ++k) a = fmaf(f[k], w1[k * 256 + c], a);
    h1[c] = fmaxf(a, 0.0f);
    __syncthreads();
    a = b2[c];
    for (int k = 0; k < 256; ++k) a = fmaf(h1[k], w2[k * 256 + c], a);
    h2[c] = fmaxf(a, 0.0f);
    __syncthreads();
    a = b3[c];
    for (int k = 0; k < 256; ++k) a = fmaf(h2[k], w3[k * 256 + c], a);
    g_obj[n * 256 + c] = a * score[n];
}

// ---------------- box corner -> grid-space edge params; reset compaction counter ------
__global__ void edge_kernel(const float* __restrict__ box)
{
    int n = threadIdx.x;
    if (n == 0) g_nact = 0;
    if (n < NBOX) {
        float gx[4], gy[4];
#pragma unroll
        for (int e = 0; e < 4; ++e) {
            gx[e] = __fdiv_rn(__fsub_rn(box[n * 24 + e * 3 + 0], -140.8f), 0.4f);
            gy[e] = __fdiv_rn(__fsub_rn(box[n * 24 + e * 3 + 1], -40.0f), 0.4f);
        }
#pragma unroll
        for (int e = 0; e < 4; ++e) {
            int e1 = (e + 1) & 3;
            g_edge[n * 16 + e * 4 + 0] = gx[e];
            g_edge[n * 16 + e * 4 + 1] = gy[e];
            g_edge[n * 16 + e * 4 + 2] = __fsub_rn(gx[e1], gx[e]);
            g_edge[n * 16 + e * 4 + 3] = __fsub_rn(gy[e1], gy[e]);
        }
    }
}

// ---------------- zero the X buffer (float4 grid-stride) ------------------------------
__global__ void zero_kernel(float4* p, int n4)
{
    int i = blockIdx.x * blockDim.x + threadIdx.x;
    int stride = gridDim.x * blockDim.x;
    for (; i < n4; i += stride) p[i] = make_float4(0.f, 0.f, 0.f, 0.f);
}

// ---------------- per-pixel inside mask + compaction ----------------------------------
__global__ void mask_kernel()
{
    __shared__ float se[NBOX * 16];
    int tid = threadIdx.x;
    for (int i = tid; i < NBOX * 16; i += blockDim.x) se[i] = g_edge[i];
    __syncthreads();

    int p = blockIdx.x * 256 + tid;
    if (p >= HW) return;
    int h = p / W;
    int w = p - h * W;
    float cy = (float)h + 0.5f;
    float cx = (float)w + 0.5f;

    unsigned mw[4];
    int cnt = 0;
#pragma unroll
    for (int wi = 0; wi < 4; ++wi) {
        unsigned m = 0;
        for (int b = 0; b < 32; ++b) {
            int n = wi * 32 + b;
            const float* e = &se[n * 16];
            bool ins = true;
#pragma unroll
            for (int k = 0; k < 4; ++k) {
                float ax = e[k * 4 + 0], ay = e[k * 4 + 1];
                float vx = e[k * 4 + 2], vy = e[k * 4 + 3];
                // mirror reference op order exactly (no FMA contraction)
                float c = __fsub_rn(__fmul_rn(vx, __fsub_rn(cy, ay)),
                                    __fmul_rn(vy, __fsub_rn(cx, ax)));
                ins = ins && (c >= 0.0f);
            }
            if (ins) m |= (1u << b);
        }
        mw[wi] = m;
        cnt += __popc(m);
    }
    if (cnt) {
        int pos = atomicAdd(&g_nact, 1);
        g_pix[pos] = p;
        g_mask[pos] = make_uint4(mw[0], mw[1], mw[2], mw[3]);
    }
}

// ---------------- scatter obj sums / counts into X (active pixels only) ---------------
__global__ void fill_kernel()
{
    int c = threadIdx.x;   // channel
    int nact = g_nact;
    for (int i = blockIdx.x; i < nact; i += gridDim.x) {
        int p = g_pix[i];
        uint4 mm = g_mask[i];
        int cnt = __popc(mm.x) + __popc(mm.y) + __popc(mm.z) + __popc(mm.w);
        float acc = 0.0f;
        unsigned m;
        m = mm.x; while (m) { int b = __ffs(m) - 1; m &= m - 1; acc += g_obj[(b)       * NC + c]; }
        m = mm.y; while (m) { int b = __ffs(m) - 1; m &= m - 1; acc += g_obj[(b + 32)  * NC + c]; }
        m = mm.z; while (m) { int b = __ffs(m) - 1; m &= m - 1; acc += g_obj[(b + 64)  * NC + c]; }
        m = mm.w; while (m) { int b = __ffs(m) - 1; m &= m - 1; acc += g_obj[(b + 96)  * NC + c]; }
        int h = p / W;
        int w = p - h * W;
        g_bufx[(size_t)c * CS + (h + 1) * WP + w + 4] = acc / (float)cnt;
    }
}

// ---------------- fused conv3x3 + BN (+residual) + ReLU -------------------------------
// Block: 256 threads. Tile: 64 co x (8h x 32w). Per thread: 8co x 8px register tile.
__global__ __launch_bounds__(256, 2)
void conv_bn_kernel(const float* __restrict__ in,
                    const float* __restrict__ wgt,
                    const float* __restrict__ bng, const float* __restrict__ bnb,
                    const float* __restrict__ bnm, const float* __restrict__ bnv,
                    const float* resid, float* out,
                    int out_cs, int out_rs, int out_roff, int out_coff, int has_res)
{
    __shared__ float sw[4 * 9 * 64];    // [ci][k][co]
    __shared__ float sx[4 * 10 * 44];   // [ci][row 0..9][col 0..33 (+pad)]

    int tid = threadIdx.x;
    int cg  = tid >> 5;       // warp id -> co subgroup (broadcast weight loads)
    int sub = tid & 31;
    int r   = sub >> 2;       // row 0..7
    int wg  = sub & 3;        // col group (8 px each)

    int co0 = blockIdx.z * 64;
    int h0  = blockIdx.y * 8;
    int w0  = blockIdx.x * 32;

    float acc[8][8];
#pragma unroll
    for (int i = 0; i < 8; ++i)
#pragma unroll
        for (int j = 0; j < 8; ++j) acc[i][j] = 0.0f;

    const float* wbase = wgt + (size_t)co0 * 2304;

    for (int cc = 0; cc < 64; ++cc) {
        int ci0 = cc << 2;
        __syncthreads();
        // stage input patch: 4ci x 10 rows x 34 cols
        for (int idx = tid; idx < 1360; idx += 256) {
            int ci = idx / 340;
            int rr = idx - ci * 340;
            int i  = rr / 34;
            int j  = rr - i * 34;
            sx[(ci * 10 + i) * 44 + j] =
                in[(size_t)(ci0 + ci) * CS + (size_t)(h0 + i) * WP + (w0 + 3) + j];
        }
        // stage weights: 64co x 4ci x 9, coalesced over 36-float runs per co
        for (int idx = tid; idx < 2304; idx += 256) {
            int co = idx / 36;
            int t  = idx - co * 36;
            int ci = t / 9;
            int k  = t - ci * 9;
            sw[(ci * 9 + k) * 64 + co] = wbase[(size_t)co * 2304 + (ci0 + ci) * 9 + k];
        }
        __syncthreads();
#pragma unroll 1
        for (int ci = 0; ci < 4; ++ci) {
#pragma unroll
            for (int kh = 0; kh < 3; ++kh) {
                const float* xr = &sx[(ci * 10 + r + kh) * 44 + (wg << 3)];
                float4 xa = *(const float4*)(xr);
                float4 xb = *(const float4*)(xr + 4);
                float2 xc = *(const float2*)(xr + 8);
                float x[10] = {xa.x, xa.y, xa.z, xa.w, xb.x, xb.y, xb.z, xb.w, xc.x, xc.y};
#pragma unroll
                for (int kw = 0; kw < 3; ++kw) {
                    const float* wr = &sw[(ci * 9 + kh * 3 + kw) * 64 + (cg << 3)];
                    float4 wa = *(const float4*)(wr);
                    float4 wb = *(const float4*)(wr + 4);
                    float wv[8] = {wa.x, wa.y, wa.z, wa.w, wb.x, wb.y, wb.z, wb.w};
#pragma unroll
                    for (int co = 0; co < 8; ++co)
#pragma unroll
                        for (int p = 0; p < 8; ++p)
                            acc[co][p] = fmaf(wv[co], x[p + kw], acc[co][p]);
                }
            }
        }
    }

    // epilogue: BN affine, optional residual, ReLU, float4 stores
    int hq  = h0 + r;
    int wq0 = w0 + (wg << 3);
#pragma unroll
    for (int co = 0; co < 8; ++co) {
        int c = co0 + (cg << 3) + co;
        float sc = bng[c] * rsqrtf(bnv[c] + 1e-5f);
        float sh = bnb[c] - bnm[c] * sc;
        float v[8];
#pragma unroll
        for (int p = 0; p < 8; ++p) v[p] = fmaf(acc[co][p], sc, sh);
        if (has_res) {
            const float* rp = resid + (size_t)c * CS + (size_t)(hq + 1) * WP + wq0 + 4;
            float4 r0 = *(const float4*)rp;
            float4 r1 = *(const float4*)(rp + 4);
            v[0] += r0.x; v[1] += r0.y; v[2] += r0.z; v[3] += r0.w;
            v[4] += r1.x; v[5] += r1.y; v[6] += r1.z; v[7] += r1.w;
        }
#pragma unroll
        for (int p = 0; p < 8; ++p) v[p] = fmaxf(v[p], 0.0f);
        float* op = out + (size_t)c * out_cs + (size_t)(hq + out_roff) * out_rs + wq0 + out_coff;
        *(float4*)(op)     = make_float4(v[0], v[1], v[2], v[3]);
        *(float4*)(op + 4) = make_float4(v[4], v[5], v[6], v[7]);
    }
}

// ---------------- host launcher -------------------------------------------------------
extern "C" void kernel_launch(void* const* d_in, const int* in_sizes, int n_in,
                              void* d_out, int out_size)
{
    const float* box   = (const float*)d_in[0];
    const float* score = (const float*)d_in[1];
    const float* w1 = (const float*)d_in[2];
    const float* b1 = (const float*)d_in[3];
    const float* w2 = (const float*)d_in[4];
    const float* b2 = (const float*)d_in[5];
    const float* w3 = (const float*)d_in[6];
    const float* b3 = (const float*)d_in[7];
    const float* cw = (const float*)d_in[8];
    const float* bg = (const float*)d_in[9];
    const float* bb = (const float*)d_in[10];
    const float* bm = (const float*)d_in[11];
    const float* bv = (const float*)d_in[12];

    float *X = nullptr, *Y = nullptr;
    cudaGetSymbolAddress((void**)&X, g_bufx);
    cudaGetSymbolAddress((void**)&Y, g_bufy);

    mlp_kernel<<<128, 256>>>(box, score, w1, b1, w2, b2, w3, b3);
    edge_kernel<<<1, 128>>>(box);
    zero_kernel<<<4096, 256>>>((float4*)X, (int)((size_t)NC * CS / 4));
    mask_kernel<<<HW / 256, 256>>>();
    fill_kernel<<<1024, 256>>>();

    dim3 cgrid(22, 25, 4);   // 704/32, 200/8, 256/64
    for (int blk = 0; blk < 3; ++blk) {
        const float* wA = cw + (size_t)(blk * 2 + 0) * NC * NC * 9;
        const float* wB = cw + (size_t)(blk * 2 + 1) * NC * NC * 9;
        int oA = (blk * 2 + 0) * NC;
        int oB = (blk * 2 + 1) * NC;
        // y = relu(bn(conv(x)))
        conv_bn_kernel<<<cgrid, 256>>>(X, wA, bg + oA, bb + oA, bm + oA, bv + oA,
                                       nullptr, Y, CS, WP, 1, 4, 0);
        // x = relu(bn(conv(y)) + x)   (last block writes unpadded d_out)
        float* op; int ocs, ors, orf, ocf;
        if (blk < 2) { op = X; ocs = CS; ors = WP; orf = 1; ocf = 4; }
        else         { op = (float*)d_out; ocs = HW; ors = W; orf = 0; ocf = 0; }
        conv_bn_kernel<<<cgrid, 256>>>(Y, wB, bg + oB, bb + oB, bm + oB, bv + oB,
                                       X, op, ocs, ors, orf, ocf, 1);
    }
}

// round 5
// speedup vs baseline: 3.0973x; 3.0835x over previous
#include <cuda_runtime.h>
#include <cuda_bf16.h>
#include <cstdint>

typedef unsigned int u32;
typedef unsigned long long u64;

#define H 200
#define W 704
#define HW_TOT (H*W)            // 140800
#define IHP 202
#define IWP 712
#define NPX ((size_t)IHP*IWP)   // padded pixels per plane
#define NCH 256
#define NBOX 128
#define NLAY 6

// ======================= persistent device scratch (zero-init at load) ==============
__device__ __align__(16) __nv_bfloat16 g_p0h[NPX*NCH], g_p0l[NPX*NCH];
__device__ __align__(16) __nv_bfloat16 g_p1h[NPX*NCH], g_p1l[NPX*NCH];
__device__ __align__(16) __nv_bfloat16 g_yh [NPX*NCH], g_yl [NPX*NCH];
__device__ __align__(16) __nv_bfloat16 g_wh[(size_t)NLAY*9*65536];
__device__ __align__(16) __nv_bfloat16 g_wl[(size_t)NLAY*9*65536];
__device__ float g_obj[NBOX*NCH];
__device__ float g_edge[NBOX*16];
__device__ int   g_nact;
__device__ int   g_pix[HW_TOT];
__device__ uint4 g_mask[HW_TOT];

// ======================= PTX helpers (all plain sm_80-class PTX) =======================
__device__ __forceinline__ u32 smem_to_u32(const void* p) {
    u32 a;
    asm("{ .reg .u64 t; cvta.to.shared.u64 t, %1; cvt.u32.u64 %0, t; }" : "=r"(a) : "l"(p));
    return a;
}
#define SWZ(o) ((o) ^ (((o) >> 3) & 0x70))

#define CP_ASYNC16(dst, src) \
    asm volatile("cp.async.cg.shared.global [%0], [%1], 16;" :: "r"(dst), "l"(src))
#define CP_COMMIT() asm volatile("cp.async.commit_group;" ::: "memory")
#define CP_WAIT1()  asm volatile("cp.async.wait_group 1;" ::: "memory")
#define CP_WAIT0()  asm volatile("cp.async.wait_group 0;" ::: "memory")

#define LDSM4(r, addr) \
    asm volatile("ldmatrix.sync.aligned.m8n8.x4.shared.b16 {%0,%1,%2,%3}, [%4];" \
        : "=r"((r)[0]), "=r"((r)[1]), "=r"((r)[2]), "=r"((r)[3]) : "r"(addr))

#define MMA16816(c, a, b0_, b1_) \
    asm volatile("mma.sync.aligned.m16n8k16.row.col.f32.bf16.bf16.f32 " \
        "{%0,%1,%2,%3},{%4,%5,%6,%7},{%8,%9},{%0,%1,%2,%3};" \
        : "+f"((c)[0]), "+f"((c)[1]), "+f"((c)[2]), "+f"((c)[3]) \
        : "r"((a)[0]), "r"((a)[1]), "r"((a)[2]), "r"((a)[3]), "r"(b0_), "r"(b1_))

__device__ __forceinline__ float bfu(u32 bits16) { return __uint_as_float(bits16 << 16); }

// ======================= MLP =======================
__global__ void mlp_kernel(const float* __restrict__ box, const float* __restrict__ score,
                           const float* __restrict__ w1, const float* __restrict__ b1,
                           const float* __restrict__ w2, const float* __restrict__ b2,
                           const float* __restrict__ w3, const float* __restrict__ b3)
{
    __shared__ float f[25];
    __shared__ float h1[256];
    __shared__ float h2[256];
    int n = blockIdx.x, c = threadIdx.x;
    if (c < 25) f[c] = (c < 24) ? box[n * 24 + c] : score[n];
    __syncthreads();
    float a = b1[c];
#pragma unroll
    for (int k = 0; k < 25; ++k) a = fmaf(f[k], w1[k * 256 + c], a);
    h1[c] = fmaxf(a, 0.0f);
    __syncthreads();
    a = b2[c];
    for (int k = 0; k < 256; ++k) a = fmaf(h1[k], w2[k * 256 + c], a);
    h2[c] = fmaxf(a, 0.0f);
    __syncthreads();
    a = b3[c];
    for (int k = 0; k < 256; ++k) a = fmaf(h2[k], w3[k * 256 + c], a);
    g_obj[n * 256 + c] = a * score[n];
}

// ======================= box edges =======================
__global__ void edge_kernel(const float* __restrict__ box)
{
    int n = threadIdx.x;
    if (n == 0) g_nact = 0;
    if (n < NBOX) {
        float gx[4], gy[4];
#pragma unroll
        for (int e = 0; e < 4; ++e) {
            gx[e] = __fdiv_rn(__fsub_rn(box[n * 24 + e * 3 + 0], -140.8f), 0.4f);
            gy[e] = __fdiv_rn(__fsub_rn(box[n * 24 + e * 3 + 1], -40.0f), 0.4f);
        }
#pragma unroll
        for (int e = 0; e < 4; ++e) {
            int e1 = (e + 1) & 3;
            g_edge[n * 16 + e * 4 + 0] = gx[e];
            g_edge[n * 16 + e * 4 + 1] = gy[e];
            g_edge[n * 16 + e * 4 + 2] = __fsub_rn(gx[e1], gx[e]);
            g_edge[n * 16 + e * 4 + 3] = __fsub_rn(gy[e1], gy[e]);
        }
    }
}

// ======================= zero p0 planes =======================
__global__ void zero2_kernel(uint4* a, uint4* b, size_t n4)
{
    size_t i = (size_t)blockIdx.x * blockDim.x + threadIdx.x;
    size_t st = (size_t)gridDim.x * blockDim.x;
    uint4 z = make_uint4(0, 0, 0, 0);
    for (; i < n4; i += st) { a[i] = z; b[i] = z; }
}

// ======================= raster mask + compaction =======================
__global__ void mask_kernel()
{
    __shared__ float se[NBOX * 16];
    int tid = threadIdx.x;
    for (int i = tid; i < NBOX * 16; i += blockDim.x) se[i] = g_edge[i];
    __syncthreads();

    int p = blockIdx.x * 256 + tid;
    if (p >= HW_TOT) return;
    int h = p / W;
    int w = p - h * W;
    float cy = (float)h + 0.5f;
    float cx = (float)w + 0.5f;

    unsigned mw[4];
    int cnt = 0;
#pragma unroll
    for (int wi = 0; wi < 4; ++wi) {
        unsigned m = 0;
        for (int b = 0; b < 32; ++b) {
            int n = wi * 32 + b;
            const float* e = &se[n * 16];
            bool ins = true;
#pragma unroll
            for (int k = 0; k < 4; ++k) {
                float ax = e[k * 4 + 0], ay = e[k * 4 + 1];
                float vx = e[k * 4 + 2], vy = e[k * 4 + 3];
                float c = __fsub_rn(__fmul_rn(vx, __fsub_rn(cy, ay)),
                                    __fmul_rn(vy, __fsub_rn(cx, ax)));
                ins = ins && (c >= 0.0f);
            }
            if (ins) m |= (1u << b);
        }
        mw[wi] = m;
        cnt += __popc(m);
    }
    if (cnt) {
        int pos = atomicAdd(&g_nact, 1);
        g_pix[pos] = p;
        g_mask[pos] = make_uint4(mw[0], mw[1], mw[2], mw[3]);
    }
}

// ======================= scatter into p0 (bf16 hi/lo NHWC) =======================
__global__ void fill_kernel()
{
    int c = threadIdx.x;
    int nact = g_nact;
    for (int i = blockIdx.x; i < nact; i += gridDim.x) {
        int p = g_pix[i];
        uint4 mm = g_mask[i];
        int cnt = __popc(mm.x) + __popc(mm.y) + __popc(mm.z) + __popc(mm.w);
        float acc = 0.0f;
        unsigned m;
        m = mm.x; while (m) { int b = __ffs(m) - 1; m &= m - 1; acc += g_obj[(b)      * NCH + c]; }
        m = mm.y; while (m) { int b = __ffs(m) - 1; m &= m - 1; acc += g_obj[(b + 32) * NCH + c]; }
        m = mm.z; while (m) { int b = __ffs(m) - 1; m &= m - 1; acc += g_obj[(b + 64) * NCH + c]; }
        m = mm.w; while (m) { int b = __ffs(m) - 1; m &= m - 1; acc += g_obj[(b + 96) * NCH + c]; }
        float v = acc / (float)cnt;
        __nv_bfloat16 hb = __float2bfloat16(v);
        __nv_bfloat16 lb = __float2bfloat16(v - __bfloat162float(hb));
        int h = p / W;
        int w = p - h * W;
        size_t o = ((size_t)(h + 1) * IWP + (w + 4)) * NCH + c;
        g_p0h[o] = hb;
        g_p0l[o] = lb;
    }
}

// ======================= weight split fp32 -> bf16 hi/lo, [layer][tap][co][ci] ========
__global__ void wsplit_kernel(const float* __restrict__ cw)
{
    int idx = blockIdx.x * 256 + threadIdx.x;
    if (idx >= NLAY * 65536) return;
    int l = idx >> 16;
    int r = idx & 65535;           // co*256 + ci
    int co = r >> 8, ci = r & 255;
    const float* src = cw + (((size_t)l * 256 + co) * 256 + ci) * 9;
#pragma unroll
    for (int t = 0; t < 9; ++t) {
        float v = src[t];
        __nv_bfloat16 hb = __float2bfloat16(v);
        __nv_bfloat16 lb = __float2bfloat16(v - __bfloat162float(hb));
        size_t dst = (size_t)(l * 9 + t) * 65536 + r;
        g_wh[dst] = hb;
        g_wl[dst] = lb;
    }
}

// ======================= mma.sync conv3x3 + BN (+res) + ReLU =======================
// CTA: 256 thr, M=128 px (one row) x N=256 co. 72 stages = 9 taps x 8 ci-chunks(32).
// Stage buffers: A 128x(Ah32|Al32) = 16KB, B 256x(Bh32|Bl32) = 32KB, double-buffered.
#define STG 49152
#define SMEM_CONV (2*STG + 2048 + 128)

__device__ __forceinline__ void issue_stage(
    u32 db, int buf, int it, int h0, int w0, int tid,
    const __nv_bfloat16* __restrict__ inH, const __nv_bfloat16* __restrict__ inL,
    const __nv_bfloat16* __restrict__ wH,  const __nv_bfloat16* __restrict__ wL)
{
    int tap = it >> 3, ch = it & 7;
    int kh = tap / 3, kw = tap - kh * 3;
    int ci0 = ch * 32;
    u32 Ab = db + buf * STG;
    u32 Bb = Ab + 16384;
    size_t abase = ((size_t)(h0 + kh) * IWP + (size_t)(w0 + 3 + kw)) * NCH + ci0;
#pragma unroll
    for (int k = 0; k < 4; ++k) {
        int idx = tid + k * 256;
        int m = idx >> 3, j = idx & 7;
        u32 dst = Ab + SWZ((u32)(m * 128 + j * 16));
        const __nv_bfloat16* src = (j < 4) ? (inH + abase + (size_t)m * NCH + j * 8)
                                           : (inL + abase + (size_t)m * NCH + (j - 4) * 8);
        CP_ASYNC16(dst, src);
    }
    size_t wbase = (size_t)tap * 65536 + ci0;
#pragma unroll
    for (int k = 0; k < 8; ++k) {
        int idx = tid + k * 256;
        int co = idx >> 3, j = idx & 7;
        u32 dst = Bb + SWZ((u32)(co * 128 + j * 16));
        const __nv_bfloat16* src = (j < 4) ? (wH + wbase + (size_t)co * NCH + j * 8)
                                           : (wL + wbase + (size_t)co * NCH + (j - 4) * 8);
        CP_ASYNC16(dst, src);
    }
}

__global__ __launch_bounds__(256, 1)
void conv_mma(const __nv_bfloat16* __restrict__ inH, const __nv_bfloat16* __restrict__ inL,
              const __nv_bfloat16* __restrict__ wH,  const __nv_bfloat16* __restrict__ wL,
              const float* __restrict__ bng, const float* __restrict__ bnb,
              const float* __restrict__ bnm, const float* __restrict__ bnv,
              const __nv_bfloat16* resH, const __nv_bfloat16* resL,
              __nv_bfloat16* outH, __nv_bfloat16* outL, float* outF)
{
    extern __shared__ char smem_raw[];
    u32 sb = smem_to_u32(smem_raw);
    u32 pd = (128u - (sb & 127u)) & 127u;
    char* dyn = smem_raw + pd;
    u32 db = sb + pd;
    float* ssc = (float*)(dyn + 2 * STG);
    float* ssh = ssc + 256;

    int tid  = threadIdx.x;
    int lane = tid & 31, warp = tid >> 5;
    int wm = warp & 3, wn = warp >> 2;
    int h0 = blockIdx.y;
    int wt = blockIdx.x;
    int w0 = (wt == 5) ? 576 : wt * 128;

    {   // BN affine per channel
        int c = tid;
        float sc = bng[c] * rsqrtf(bnv[c] + 1e-5f);
        ssc[c] = sc;
        ssh[c] = bnb[c] - bnm[c] * sc;
    }

    float acc[2][16][4];
#pragma unroll
    for (int a = 0; a < 2; ++a)
#pragma unroll
        for (int b = 0; b < 16; ++b)
#pragma unroll
            for (int c = 0; c < 4; ++c) acc[a][b][c] = 0.0f;

    issue_stage(db, 0, 0, h0, w0, tid, inH, inL, wH, wL);
    CP_COMMIT();

    for (int it = 0; it < 72; ++it) {
        if (it + 1 < 72) {
            issue_stage(db, (it + 1) & 1, it + 1, h0, w0, tid, inH, inL, wH, wL);
            CP_COMMIT();
            CP_WAIT1();
        } else {
            CP_WAIT0();
        }
        __syncthreads();

        u32 Ab = db + (it & 1) * STG;
        u32 Bb = Ab + 16384;
        int lrow = lane & 15;
        int lkb  = (lane >> 4) << 4;       // 0 or 16 bytes (k0/k8)
#pragma unroll
        for (int pass = 0; pass < 3; ++pass) {
            int ao = (pass == 1) ? 64 : 0;   // A half: lo at +32ci = 64B
            int bo = (pass == 2) ? 64 : 0;   // B half
#pragma unroll
            for (int st = 0; st < 2; ++st) {
                int akb = ao + st * 32 + lkb;
                int bkb = bo + st * 32 + lkb;
                u32 afr[2][4];
#pragma unroll
                for (int mf = 0; mf < 2; ++mf) {
                    int m = wm * 32 + mf * 16 + lrow;
                    u32 ad = Ab + SWZ((u32)(m * 128 + akb));
                    LDSM4(afr[mf], ad);
                }
#pragma unroll
                for (int bp = 0; bp < 8; ++bp) {
                    u32 bfr[4];
                    int n = wn * 128 + bp * 16 + lrow;
                    u32 bd = Bb + SWZ((u32)(n * 128 + bkb));
                    LDSM4(bfr, bd);
#pragma unroll
                    for (int mf = 0; mf < 2; ++mf) {
                        MMA16816(acc[mf][2 * bp],     afr[mf], bfr[0], bfr[2]);
                        MMA16816(acc[mf][2 * bp + 1], afr[mf], bfr[1], bfr[3]);
                    }
                }
            }
        }
        __syncthreads();
    }

    // ---- epilogue: BN, residual, ReLU, store ----
#pragma unroll
    for (int mf = 0; mf < 2; ++mf) {
#pragma unroll
        for (int r2 = 0; r2 < 2; ++r2) {
            int m = wm * 32 + mf * 16 + (lane >> 2) + r2 * 8;
            int wpix = w0 + m;
            size_t pb = ((size_t)(h0 + 1) * IWP + (size_t)(wpix + 4)) * NCH;
#pragma unroll
            for (int bp = 0; bp < 16; ++bp) {
                int n = wn * 128 + bp * 8 + (lane & 3) * 2;
                float v0 = fmaf(acc[mf][bp][r2 * 2 + 0], ssc[n],     ssh[n]);
                float v1 = fmaf(acc[mf][bp][r2 * 2 + 1], ssc[n + 1], ssh[n + 1]);
                if (resH) {
                    u32 rh = *(const u32*)((const char*)resH + (pb + n) * 2);
                    u32 rl = *(const u32*)((const char*)resL + (pb + n) * 2);
                    v0 += bfu(rh & 0xffffu) + bfu(rl & 0xffffu);
                    v1 += bfu(rh >> 16)     + bfu(rl >> 16);
                }
                v0 = fmaxf(v0, 0.0f);
                v1 = fmaxf(v1, 0.0f);
                if (outH) {
                    __nv_bfloat16 hb0 = __float2bfloat16(v0);
                    __nv_bfloat16 hb1 = __float2bfloat16(v1);
                    __nv_bfloat16 lb0 = __float2bfloat16(v0 - __bfloat162float(hb0));
                    __nv_bfloat16 lb1 = __float2bfloat16(v1 - __bfloat162float(hb1));
                    u32 hp = (u32)__bfloat16_as_ushort(hb0) | ((u32)__bfloat16_as_ushort(hb1) << 16);
                    u32 lp = (u32)__bfloat16_as_ushort(lb0) | ((u32)__bfloat16_as_ushort(lb1) << 16);
                    *(u32*)((char*)outH + (pb + n) * 2) = hp;
                    *(u32*)((char*)outL + (pb + n) * 2) = lp;
                } else {
                    outF[(size_t)n * HW_TOT       + (size_t)h0 * W + wpix] = v0;
                    outF[(size_t)(n + 1) * HW_TOT + (size_t)h0 * W + wpix] = v1;
                }
            }
        }
    }
}

// ======================= host launcher =======================
extern "C" void kernel_launch(void* const* d_in, const int* in_sizes, int n_in,
                              void* d_out, int out_size)
{
    const float* box   = (const float*)d_in[0];
    const float* score = (const float*)d_in[1];
    const float* w1 = (const float*)d_in[2];
    const float* b1 = (const float*)d_in[3];
    const float* w2 = (const float*)d_in[4];
    const float* b2 = (const float*)d_in[5];
    const float* w3 = (const float*)d_in[6];
    const float* b3 = (const float*)d_in[7];
    const float* cw = (const float*)d_in[8];
    const float* bg = (const float*)d_in[9];
    const float* bb = (const float*)d_in[10];
    const float* bm = (const float*)d_in[11];
    const float* bv = (const float*)d_in[12];

    cudaFuncSetAttribute(conv_mma, cudaFuncAttributeMaxDynamicSharedMemorySize, SMEM_CONV);

    __nv_bfloat16 *p0h, *p0l, *p1h, *p1l, *yh, *yl, *wh, *wl;
    cudaGetSymbolAddress((void**)&p0h, g_p0h);
    cudaGetSymbolAddress((void**)&p0l, g_p0l);
    cudaGetSymbolAddress((void**)&p1h, g_p1h);
    cudaGetSymbolAddress((void**)&p1l, g_p1l);
    cudaGetSymbolAddress((void**)&yh,  g_yh);
    cudaGetSymbolAddress((void**)&yl,  g_yl);
    cudaGetSymbolAddress((void**)&wh,  g_wh);
    cudaGetSymbolAddress((void**)&wl,  g_wl);

    mlp_kernel<<<128, 256>>>(box, score, w1, b1, w2, b2, w3, b3);
    edge_kernel<<<1, 128>>>(box);
    wsplit_kernel<<<(NLAY * 65536 + 255) / 256, 256>>>(cw);
    zero2_kernel<<<2048, 256>>>((uint4*)p0h, (uint4*)p0l, NPX * NCH / 8);
    mask_kernel<<<HW_TOT / 256, 256>>>();
    fill_kernel<<<1024, 256>>>();

    dim3 grid(6, 200);
    const size_t WSTRIDE = (size_t)9 * 65536;
    // blk0: p0 -> y ; (y, res p0) -> p1
    conv_mma<<<grid, 256, SMEM_CONV>>>(p0h, p0l, wh + 0 * WSTRIDE, wl + 0 * WSTRIDE,
        bg + 0, bb + 0, bm + 0, bv + 0, nullptr, nullptr, yh, yl, nullptr);
    conv_mma<<<grid, 256, SMEM_CONV>>>(yh, yl, wh + 1 * WSTRIDE, wl + 1 * WSTRIDE,
        bg + 256, bb + 256, bm + 256, bv + 256, p0h, p0l, p1h, p1l, nullptr);
    // blk1: p1 -> y ; (y, res p1) -> p0
    conv_mma<<<grid, 256, SMEM_CONV>>>(p1h, p1l, wh + 2 * WSTRIDE, wl + 2 * WSTRIDE,
        bg + 512, bb + 512, bm + 512, bv + 512, nullptr, nullptr, yh, yl, nullptr);
    conv_mma<<<grid, 256, SMEM_CONV>>>(yh, yl, wh + 3 * WSTRIDE, wl + 3 * WSTRIDE,
        bg + 768, bb + 768, bm + 768, bv + 768, p1h, p1l, p0h, p0l, nullptr);
    // blk2: p0 -> y ; (y, res p0) -> d_out (fp32 NCHW)
    conv_mma<<<grid, 256, SMEM_CONV>>>(p0h, p0l, wh + 4 * WSTRIDE, wl + 4 * WSTRIDE,
        bg + 1024, bb + 1024, bm + 1024, bv + 1024, nullptr, nullptr, yh, yl, nullptr);
    conv_mma<<<grid, 256, SMEM_CONV>>>(yh, yl, wh + 5 * WSTRIDE, wl + 5 * WSTRIDE,
        bg + 1280, bb + 1280, bm + 1280, bv + 1280, p0h, p0l, nullptr, nullptr, (float*)d_out);
}

// round 6
// speedup vs baseline: 3.4000x; 1.0977x over previous
#include <cuda_runtime.h>
#include <cuda_bf16.h>
#include <cstdint>

typedef unsigned int u32;
typedef unsigned long long u64;

#define H 200
#define W 704
#define HW_TOT (H*W)            // 140800
#define IHP 202
#define IWP 712
#define NPX ((size_t)IHP*IWP)   // padded pixels per plane
#define NCH 256
#define NBOX 128
#define NLAY 6

// ======================= persistent device scratch (zero-init at load) ==============
__device__ __align__(16) __nv_bfloat16 g_p0h[NPX*NCH], g_p0l[NPX*NCH];
__device__ __align__(16) __nv_bfloat16 g_p1h[NPX*NCH], g_p1l[NPX*NCH];
__device__ __align__(16) __nv_bfloat16 g_yh [NPX*NCH], g_yl [NPX*NCH];
__device__ __align__(16) __nv_bfloat16 g_wh[(size_t)NLAY*9*65536];
__device__ __align__(16) __nv_bfloat16 g_wl[(size_t)NLAY*9*65536];
__device__ float g_obj[NBOX*NCH];
__device__ float g_edge[NBOX*16];
__device__ int   g_nact;
__device__ int   g_pix[HW_TOT];
__device__ uint4 g_mask[HW_TOT];

// ======================= PTX helpers (plain sm_80-class PTX) =======================
__device__ __forceinline__ u32 smem_to_u32(const void* p) {
    u32 a;
    asm("{ .reg .u64 t; cvta.to.shared.u64 t, %1; cvt.u32.u64 %0, t; }" : "=r"(a) : "l"(p));
    return a;
}
#define SWZ(o) ((o) ^ (((o) >> 3) & 0x70))

#define CP_ASYNC16(dst, src) \
    asm volatile("cp.async.cg.shared.global [%0], [%1], 16;" :: "r"(dst), "l"(src))
#define CP_COMMIT() asm volatile("cp.async.commit_group;" ::: "memory")
#define CP_WAIT1()  asm volatile("cp.async.wait_group 1;" ::: "memory")
#define CP_WAIT0()  asm volatile("cp.async.wait_group 0;" ::: "memory")

#define LDSM4(r, addr) \
    asm volatile("ldmatrix.sync.aligned.m8n8.x4.shared.b16 {%0,%1,%2,%3}, [%4];" \
        : "=r"((r)[0]), "=r"((r)[1]), "=r"((r)[2]), "=r"((r)[3]) : "r"(addr))

#define MMA16816(c, a, b0_, b1_) \
    asm volatile("mma.sync.aligned.m16n8k16.row.col.f32.bf16.bf16.f32 " \
        "{%0,%1,%2,%3},{%4,%5,%6,%7},{%8,%9},{%0,%1,%2,%3};" \
        : "+f"((c)[0]), "+f"((c)[1]), "+f"((c)[2]), "+f"((c)[3]) \
        : "r"((a)[0]), "r"((a)[1]), "r"((a)[2]), "r"((a)[3]), "r"(b0_), "r"(b1_))

__device__ __forceinline__ float bfu(u32 bits16) { return __uint_as_float(bits16 << 16); }

// ======================= MLP =======================
__global__ void mlp_kernel(const float* __restrict__ box, const float* __restrict__ score,
                           const float* __restrict__ w1, const float* __restrict__ b1,
                           const float* __restrict__ w2, const float* __restrict__ b2,
                           const float* __restrict__ w3, const float* __restrict__ b3)
{
    __shared__ float f[25];
    __shared__ float h1[256];
    __shared__ float h2[256];
    int n = blockIdx.x, c = threadIdx.x;
    if (c < 25) f[c] = (c < 24) ? box[n * 24 + c] : score[n];
    __syncthreads();
    float a = b1[c];
#pragma unroll
    for (int k = 0; k < 25; ++k) a = fmaf(f[k], w1[k * 256 + c], a);
    h1[c] = fmaxf(a, 0.0f);
    __syncthreads();
    a = b2[c];
    for (int k = 0; k < 256; ++k) a = fmaf(h1[k], w2[k * 256 + c], a);
    h2[c] = fmaxf(a, 0.0f);
    __syncthreads();
    a = b3[c];
    for (int k = 0; k < 256; ++k) a = fmaf(h2[k], w3[k * 256 + c], a);
    g_obj[n * 256 + c] = a * score[n];
}

// ======================= box edges =======================
__global__ void edge_kernel(const float* __restrict__ box)
{
    int n = threadIdx.x;
    if (n == 0) g_nact = 0;
    if (n < NBOX) {
        float gx[4], gy[4];
#pragma unroll
        for (int e = 0; e < 4; ++e) {
            gx[e] = __fdiv_rn(__fsub_rn(box[n * 24 + e * 3 + 0], -140.8f), 0.4f);
            gy[e] = __fdiv_rn(__fsub_rn(box[n * 24 + e * 3 + 1], -40.0f), 0.4f);
        }
#pragma unroll
        for (int e = 0; e < 4; ++e) {
            int e1 = (e + 1) & 3;
            g_edge[n * 16 + e * 4 + 0] = gx[e];
            g_edge[n * 16 + e * 4 + 1] = gy[e];
            g_edge[n * 16 + e * 4 + 2] = __fsub_rn(gx[e1], gx[e]);
            g_edge[n * 16 + e * 4 + 3] = __fsub_rn(gy[e1], gy[e]);
        }
    }
}

// ======================= zero p0 planes =======================
__global__ void zero2_kernel(uint4* a, uint4* b, size_t n4)
{
    size_t i = (size_t)blockIdx.x * blockDim.x + threadIdx.x;
    size_t st = (size_t)gridDim.x * blockDim.x;
    uint4 z = make_uint4(0, 0, 0, 0);
    for (; i < n4; i += st) { a[i] = z; b[i] = z; }
}

// ======================= raster mask + compaction =======================
__global__ void mask_kernel()
{
    __shared__ float se[NBOX * 16];
    int tid = threadIdx.x;
    for (int i = tid; i < NBOX * 16; i += blockDim.x) se[i] = g_edge[i];
    __syncthreads();

    int p = blockIdx.x * 256 + tid;
    if (p >= HW_TOT) return;
    int h = p / W;
    int w = p - h * W;
    float cy = (float)h + 0.5f;
    float cx = (float)w + 0.5f;

    unsigned mw[4];
    int cnt = 0;
#pragma unroll
    for (int wi = 0; wi < 4; ++wi) {
        unsigned m = 0;
        for (int b = 0; b < 32; ++b) {
            int n = wi * 32 + b;
            const float* e = &se[n * 16];
            bool ins = true;
#pragma unroll
            for (int k = 0; k < 4; ++k) {
                float ax = e[k * 4 + 0], ay = e[k * 4 + 1];
                float vx = e[k * 4 + 2], vy = e[k * 4 + 3];
                float c = __fsub_rn(__fmul_rn(vx, __fsub_rn(cy, ay)),
                                    __fmul_rn(vy, __fsub_rn(cx, ax)));
                ins = ins && (c >= 0.0f);
            }
            if (ins) m |= (1u << b);
        }
        mw[wi] = m;
        cnt += __popc(m);
    }
    if (cnt) {
        int pos = atomicAdd(&g_nact, 1);
        g_pix[pos] = p;
        g_mask[pos] = make_uint4(mw[0], mw[1], mw[2], mw[3]);
    }
}

// ======================= scatter into p0 (bf16 hi/lo NHWC) =======================
__global__ void fill_kernel()
{
    int c = threadIdx.x;
    int nact = g_nact;
    for (int i = blockIdx.x; i < nact; i += gridDim.x) {
        int p = g_pix[i];
        uint4 mm = g_mask[i];
        int cnt = __popc(mm.x) + __popc(mm.y) + __popc(mm.z) + __popc(mm.w);
        float acc = 0.0f;
        unsigned m;
        m = mm.x; while (m) { int b = __ffs(m) - 1; m &= m - 1; acc += g_obj[(b)      * NCH + c]; }
        m = mm.y; while (m) { int b = __ffs(m) - 1; m &= m - 1; acc += g_obj[(b + 32) * NCH + c]; }
        m = mm.z; while (m) { int b = __ffs(m) - 1; m &= m - 1; acc += g_obj[(b + 64) * NCH + c]; }
        m = mm.w; while (m) { int b = __ffs(m) - 1; m &= m - 1; acc += g_obj[(b + 96) * NCH + c]; }
        float v = acc / (float)cnt;
        __nv_bfloat16 hb = __float2bfloat16(v);
        __nv_bfloat16 lb = __float2bfloat16(v - __bfloat162float(hb));
        int h = p / W;
        int w = p - h * W;
        size_t o = ((size_t)(h + 1) * IWP + (w + 4)) * NCH + c;
        g_p0h[o] = hb;
        g_p0l[o] = lb;
    }
}

// ======================= weight split fp32 -> bf16 hi/lo, [layer][tap][co][ci] ========
__global__ void wsplit_kernel(const float* __restrict__ cw)
{
    int idx = blockIdx.x * 256 + threadIdx.x;
    if (idx >= NLAY * 65536) return;
    int l = idx >> 16;
    int r = idx & 65535;           // co*256 + ci
    int co = r >> 8, ci = r & 255;
    const float* src = cw + (((size_t)l * 256 + co) * 256 + ci) * 9;
#pragma unroll
    for (int t = 0; t < 9; ++t) {
        float v = src[t];
        __nv_bfloat16 hb = __float2bfloat16(v);
        __nv_bfloat16 lb = __float2bfloat16(v - __bfloat162float(hb));
        size_t dst = (size_t)(l * 9 + t) * 65536 + r;
        g_wh[dst] = hb;
        g_wl[dst] = lb;
    }
}

// ======================= mma.sync conv3x3 + BN (+res) + ReLU =======================
// CTA: 256 thr (8 warps, 2 wm x 4 wn; warp tile m=64 x n=64).
// M=128 px (one output row) x N=256 co. 36 stages = 9 taps x 4 ci-chunks(64).
// Stage: Ah 16K | Al 16K | Bh 32K | Bl 32K = 96KB, double buffered (192KB).
#define STG 98304
#define SMEM_CONV (2*STG + 2048 + 128)

__device__ __forceinline__ void issue_stage(
    u32 db, int buf, int it, int h0, int w0, int tid,
    const __nv_bfloat16* __restrict__ inH, const __nv_bfloat16* __restrict__ inL,
    const __nv_bfloat16* __restrict__ wH,  const __nv_bfloat16* __restrict__ wL)
{
    int tap = it >> 2, q = it & 3;
    int kh = tap / 3, kw = tap - kh * 3;
    int ci0 = q * 64;
    u32 Ab = db + buf * STG;
    u32 Bb = Ab + 32768;
    size_t abase = ((size_t)(h0 + kh) * IWP + (size_t)(w0 + 3 + kw)) * NCH + ci0;
#pragma unroll
    for (int k = 0; k < 4; ++k) {
        int idx = tid + k * 256;           // 0..1023
        int m = idx >> 3, j = idx & 7;
        u32 off = SWZ((u32)(m * 128 + j * 16));
        const __nv_bfloat16* sh = inH + abase + (size_t)m * NCH + j * 8;
        const __nv_bfloat16* sl = inL + abase + (size_t)m * NCH + j * 8;
        CP_ASYNC16(Ab + off,         sh);
        CP_ASYNC16(Ab + 16384 + off, sl);
    }
    size_t wbase = (size_t)tap * 65536 + ci0;
#pragma unroll
    for (int k = 0; k < 8; ++k) {
        int idx = tid + k * 256;           // 0..2047
        int co = idx >> 3, j = idx & 7;
        u32 off = SWZ((u32)(co * 128 + j * 16));
        const __nv_bfloat16* sh = wH + wbase + (size_t)co * NCH + j * 8;
        const __nv_bfloat16* sl = wL + wbase + (size_t)co * NCH + j * 8;
        CP_ASYNC16(Bb + off,         sh);
        CP_ASYNC16(Bb + 32768 + off, sl);
    }
}

__global__ __launch_bounds__(256, 1)
void conv_mma(const __nv_bfloat16* __restrict__ inH, const __nv_bfloat16* __restrict__ inL,
              const __nv_bfloat16* __restrict__ wH,  const __nv_bfloat16* __restrict__ wL,
              const float* __restrict__ bng, const float* __restrict__ bnb,
              const float* __restrict__ bnm, const float* __restrict__ bnv,
              const __nv_bfloat16* resH, const __nv_bfloat16* resL,
              __nv_bfloat16* outH, __nv_bfloat16* outL, float* outF)
{
    extern __shared__ char smem_raw[];
    u32 sb = smem_to_u32(smem_raw);
    u32 pd = (128u - (sb & 127u)) & 127u;
    char* dyn = smem_raw + pd;
    u32 db = sb + pd;
    float* ssc = (float*)(dyn + 2 * STG);
    float* ssh = ssc + 256;

    int tid  = threadIdx.x;
    int lane = tid & 31, warp = tid >> 5;
    int wm = warp & 1, wn = warp >> 1;          // 2 x 4 warp grid
    int h0 = blockIdx.y;
    int wt = blockIdx.x;
    int w0 = (wt == 5) ? 576 : wt * 128;

    {   // BN affine per channel
        int c = tid;
        float sc = bng[c] * rsqrtf(bnv[c] + 1e-5f);
        ssc[c] = sc;
        ssh[c] = bnb[c] - bnm[c] * sc;
    }

    float acc[4][8][4];
#pragma unroll
    for (int a = 0; a < 4; ++a)
#pragma unroll
        for (int b = 0; b < 8; ++b)
#pragma unroll
            for (int c = 0; c < 4; ++c) acc[a][b][c] = 0.0f;

    issue_stage(db, 0, 0, h0, w0, tid, inH, inL, wH, wL);
    CP_COMMIT();

    int lrow = lane & 15;
    int lkb  = (lane >> 4) << 4;       // 0 or 16 bytes (k0/k8)

    for (int it = 0; it < 36; ++it) {
        if (it + 1 < 36) {
            issue_stage(db, (it + 1) & 1, it + 1, h0, w0, tid, inH, inL, wH, wL);
            CP_COMMIT();
            CP_WAIT1();
        } else {
            CP_WAIT0();
        }
        __syncthreads();

        u32 base = db + (it & 1) * STG;
        u32 Ah = base, Al = base + 16384, Bh = base + 32768, Bl = base + 65536;

        // --- passes 1+2: (Ah + Al) x Bh, B fragment loaded once per bp ---
#pragma unroll
        for (int st = 0; st < 4; ++st) {
            int kb = st * 32 + lkb;
            u32 afh[4][4], afl[4][4];
#pragma unroll
            for (int mf = 0; mf < 4; ++mf) {
                u32 ro = SWZ((u32)((wm * 64 + mf * 16 + lrow) * 128 + kb));
                LDSM4(afh[mf], Ah + ro);
                LDSM4(afl[mf], Al + ro);
            }
#pragma unroll
            for (int bp = 0; bp < 4; ++bp) {
                u32 bf[4];
                LDSM4(bf, Bh + SWZ((u32)((wn * 64 + bp * 16 + lrow) * 128 + kb)));
#pragma unroll
                for (int mf = 0; mf < 4; ++mf) {
                    MMA16816(acc[mf][2 * bp],     afh[mf], bf[0], bf[2]);
                    MMA16816(acc[mf][2 * bp + 1], afh[mf], bf[1], bf[3]);
                }
#pragma unroll
                for (int mf = 0; mf < 4; ++mf) {
                    MMA16816(acc[mf][2 * bp],     afl[mf], bf[0], bf[2]);
                    MMA16816(acc[mf][2 * bp + 1], afl[mf], bf[1], bf[3]);
                }
            }
        }
        // --- pass 3: Ah x Bl ---
#pragma unroll
        for (int st = 0; st < 4; ++st) {
            int kb = st * 32 + lkb;
            u32 afh[4][4];
#pragma unroll
            for (int mf = 0; mf < 4; ++mf)
                LDSM4(afh[mf], Ah + SWZ((u32)((wm * 64 + mf * 16 + lrow) * 128 + kb)));
#pragma unroll
            for (int bp = 0; bp < 4; ++bp) {
                u32 bf[4];
                LDSM4(bf, Bl + SWZ((u32)((wn * 64 + bp * 16 + lrow) * 128 + kb)));
#pragma unroll
                for (int mf = 0; mf < 4; ++mf) {
                    MMA16816(acc[mf][2 * bp],     afh[mf], bf[0], bf[2]);
                    MMA16816(acc[mf][2 * bp + 1], afh[mf], bf[1], bf[3]);
                }
            }
        }
        __syncthreads();
    }

    // ---- epilogue: BN, residual, ReLU, store ----
#pragma unroll
    for (int mf = 0; mf < 4; ++mf) {
#pragma unroll
        for (int r2 = 0; r2 < 2; ++r2) {
            int m = wm * 64 + mf * 16 + (lane >> 2) + r2 * 8;
            int wpix = w0 + m;
            size_t pb = ((size_t)(h0 + 1) * IWP + (size_t)(wpix + 4)) * NCH;
#pragma unroll
            for (int a = 0; a < 8; ++a) {
                int n = wn * 64 + a * 8 + (lane & 3) * 2;
                float v0 = fmaf(acc[mf][a][r2 * 2 + 0], ssc[n],     ssh[n]);
                float v1 = fmaf(acc[mf][a][r2 * 2 + 1], ssc[n + 1], ssh[n + 1]);
                if (resH) {
                    u32 rh = *(const u32*)((const char*)resH + (pb + n) * 2);
                    u32 rl = *(const u32*)((const char*)resL + (pb + n) * 2);
                    v0 += bfu(rh & 0xffffu) + bfu(rl & 0xffffu);
                    v1 += bfu(rh >> 16)     + bfu(rl >> 16);
                }
                v0 = fmaxf(v0, 0.0f);
                v1 = fmaxf(v1, 0.0f);
                if (outH) {
                    __nv_bfloat16 hb0 = __float2bfloat16(v0);
                    __nv_bfloat16 hb1 = __float2bfloat16(v1);
                    __nv_bfloat16 lb0 = __float2bfloat16(v0 - __bfloat162float(hb0));
                    __nv_bfloat16 lb1 = __float2bfloat16(v1 - __bfloat162float(hb1));
                    u32 hp = (u32)__bfloat16_as_ushort(hb0) | ((u32)__bfloat16_as_ushort(hb1) << 16);
                    u32 lp = (u32)__bfloat16_as_ushort(lb0) | ((u32)__bfloat16_as_ushort(lb1) << 16);
                    *(u32*)((char*)outH + (pb + n) * 2) = hp;
                    *(u32*)((char*)outL + (pb + n) * 2) = lp;
                } else {
                    outF[(size_t)n * HW_TOT       + (size_t)h0 * W + wpix] = v0;
                    outF[(size_t)(n + 1) * HW_TOT + (size_t)h0 * W + wpix] = v1;
                }
            }
        }
    }
}

// ======================= host launcher =======================
extern "C" void kernel_launch(void* const* d_in, const int* in_sizes, int n_in,
                              void* d_out, int out_size)
{
    const float* box   = (const float*)d_in[0];
    const float* score = (const float*)d_in[1];
    const float* w1 = (const float*)d_in[2];
    const float* b1 = (const float*)d_in[3];
    const float* w2 = (const float*)d_in[4];
    const float* b2 = (const float*)d_in[5];
    const float* w3 = (const float*)d_in[6];
    const float* b3 = (const float*)d_in[7];
    const float* cw = (const float*)d_in[8];
    const float* bg = (const float*)d_in[9];
    const float* bb = (const float*)d_in[10];
    const float* bm = (const float*)d_in[11];
    const float* bv = (const float*)d_in[12];

    cudaFuncSetAttribute(conv_mma, cudaFuncAttributeMaxDynamicSharedMemorySize, SMEM_CONV);

    __nv_bfloat16 *p0h, *p0l, *p1h, *p1l, *yh, *yl, *wh, *wl;
    cudaGetSymbolAddress((void**)&p0h, g_p0h);
    cudaGetSymbolAddress((void**)&p0l, g_p0l);
    cudaGetSymbolAddress((void**)&p1h, g_p1h);
    cudaGetSymbolAddress((void**)&p1l, g_p1l);
    cudaGetSymbolAddress((void**)&yh,  g_yh);
    cudaGetSymbolAddress((void**)&yl,  g_yl);
    cudaGetSymbolAddress((void**)&wh,  g_wh);
    cudaGetSymbolAddress((void**)&wl,  g_wl);

    mlp_kernel<<<128, 256>>>(box, score, w1, b1, w2, b2, w3, b3);
    edge_kernel<<<1, 128>>>(box);
    wsplit_kernel<<<(NLAY * 65536 + 255) / 256, 256>>>(cw);
    zero2_kernel<<<2048, 256>>>((uint4*)p0h, (uint4*)p0l, NPX * NCH / 8);
    mask_kernel<<<HW_TOT / 256, 256>>>();
    fill_kernel<<<1024, 256>>>();

    dim3 grid(6, 200);
    const size_t WSTRIDE = (size_t)9 * 65536;
    // blk0: p0 -> y ; (y, res p0) -> p1
    conv_mma<<<grid, 256, SMEM_CONV>>>(p0h, p0l, wh + 0 * WSTRIDE, wl + 0 * WSTRIDE,
        bg + 0, bb + 0, bm + 0, bv + 0, nullptr, nullptr, yh, yl, nullptr);
    conv_mma<<<grid, 256, SMEM_CONV>>>(yh, yl, wh + 1 * WSTRIDE, wl + 1 * WSTRIDE,
        bg + 256, bb + 256, bm + 256, bv + 256, p0h, p0l, p1h, p1l, nullptr);
    // blk1: p1 -> y ; (y, res p1) -> p0
    conv_mma<<<grid, 256, SMEM_CONV>>>(p1h, p1l, wh + 2 * WSTRIDE, wl + 2 * WSTRIDE,
        bg + 512, bb + 512, bm + 512, bv + 512, nullptr, nullptr, yh, yl, nullptr);
    conv_mma<<<grid, 256, SMEM_CONV>>>(yh, yl, wh + 3 * WSTRIDE, wl + 3 * WSTRIDE,
        bg + 768, bb + 768, bm + 768, bv + 768, p1h, p1l, p0h, p0l, nullptr);
    // blk2: p0 -> y ; (y, res p0) -> d_out (fp32 NCHW)
    conv_mma<<<grid, 256, SMEM_CONV>>>(p0h, p0l, wh + 4 * WSTRIDE, wl + 4 * WSTRIDE,
        bg + 1024, bb + 1024, bm + 1024, bv + 1024, nullptr, nullptr, yh, yl, nullptr);
    conv_mma<<<grid, 256, SMEM_CONV>>>(yh, yl, wh + 5 * WSTRIDE, wl + 5 * WSTRIDE,
        bg + 1280, bb + 1280, bm + 1280, bv + 1280, p0h, p0l, nullptr, nullptr, (float*)d_out);
}